// round 14
// baseline (speedup 1.0000x reference)
#include <cuda_runtime.h>
#include <cuda_bf16.h>
#include <math.h>
#include <cstdint>

#define BB 2
#define SS 2048
#define DD 4096
#define QKVN 6144
#define HKV 8
#define NH 32
#define HD 128

// ---------------- scratch (static device globals; no runtime allocation) ----------------
__device__ float g_qkv[(size_t)BB * SS * QKVN];            // fp32, feeds rope
__device__ float g_scores[(size_t)BB * NH * SS * SS];      // fp32, feeds softmax
// hi/lo bf16 operand arrays
__device__ __nv_bfloat16 g_hh[(size_t)BB * SS * DD];       // hidden hi
__device__ __nv_bfloat16 g_hl[(size_t)BB * SS * DD];       // hidden lo
__device__ __nv_bfloat16 g_wqh[(size_t)QKVN * DD];
__device__ __nv_bfloat16 g_wql[(size_t)QKVN * DD];
__device__ __nv_bfloat16 g_woh[(size_t)DD * DD];
__device__ __nv_bfloat16 g_wol[(size_t)DD * DD];
__device__ __nv_bfloat16 g_qh[(size_t)BB * NH * SS * HD];
__device__ __nv_bfloat16 g_ql[(size_t)BB * NH * SS * HD];
__device__ __nv_bfloat16 g_kh[(size_t)BB * HKV * SS * HD];
__device__ __nv_bfloat16 g_kl[(size_t)BB * HKV * SS * HD];
__device__ __nv_bfloat16 g_vth[(size_t)BB * HKV * HD * SS];   // V transposed [b,kv,d,s]
__device__ __nv_bfloat16 g_vtl[(size_t)BB * HKV * HD * SS];
__device__ __nv_bfloat16 g_ph[(size_t)BB * NH * SS * SS];     // softmax probs hi
__device__ __nv_bfloat16 g_pl[(size_t)BB * NH * SS * SS];     // softmax probs lo
__device__ __nv_bfloat16 g_ah[(size_t)BB * SS * DD];          // attn out hi [B,S,32,HD]
__device__ __nv_bfloat16 g_al[(size_t)BB * SS * DD];          // attn out lo

// ================= helpers =================
__device__ __forceinline__ uint32_t smem_to_u32(const void* smem_ptr) {
    uint32_t addr;
    asm("{ .reg .u64 tmp; cvta.to.shared.u64 tmp, %1; cvt.u32.u64 %0, tmp; }"
        : "=r"(addr) : "l"(smem_ptr));
    return addr;
}

__device__ __forceinline__ void cp_async16(uint32_t saddr, const void* gptr) {
    asm volatile("cp.async.cg.shared.global [%0], [%1], 16;" :: "r"(saddr), "l"(gptr));
}
__device__ __forceinline__ void cp_commit() {
    asm volatile("cp.async.commit_group;" ::: "memory");
}
template <int N>
__device__ __forceinline__ void cp_wait() {
    asm volatile("cp.async.wait_group %0;" :: "n"(N) : "memory");
}

// ldmatrix x4: four 8x8 b16 matrices, lane L supplies one 16B row address
__device__ __forceinline__ void ldsm4(uint32_t* r, uint32_t addr) {
    asm volatile("ldmatrix.sync.aligned.m8n8.x4.shared.b16 {%0,%1,%2,%3}, [%4];"
        : "=r"(r[0]), "=r"(r[1]), "=r"(r[2]), "=r"(r[3]) : "r"(addr));
}

// m16n8k16 bf16 MMA, fp32 accumulate
__device__ __forceinline__ void mma_bf16(float* d, const uint32_t* a, const uint32_t* b) {
    asm volatile(
        "mma.sync.aligned.m16n8k16.row.col.f32.bf16.bf16.f32 "
        "{%0,%1,%2,%3}, {%4,%5,%6,%7}, {%8,%9}, {%0,%1,%2,%3};"
        : "+f"(d[0]), "+f"(d[1]), "+f"(d[2]), "+f"(d[3])
        : "r"(a[0]), "r"(a[1]), "r"(a[2]), "r"(a[3]),
          "r"(b[0]), "r"(b[1]));
}

__device__ __forceinline__ void split_bf16(float v, __nv_bfloat16& h, __nv_bfloat16& l) {
    h = __float2bfloat16(v);
    l = __float2bfloat16(v - __bfloat162float(h));
}

// ======================================================================================
// tc_gemm256: CTA tile 128x256, warp tile 64x64 (8 warps, 2M x 4N), 1 CTA/SM.
// Stage: Ah(8K) Al(8K) Bh(16K) Bl(16K) = 48KB; 3 stages = 144KB.
// Rows are 32 bf16 = 64B; swizzle: 16B-chunk index ^= (row>>1)&3  (invariant under +64 rows).
// ======================================================================================
#define STAGE256 49152u
static constexpr uint32_t SM_TOTAL256 = 3u * STAGE256;     // 147456

__device__ __forceinline__ void stage256(
    uint32_t sb, int koff, uint32_t sdst0,
    const __nv_bfloat16* pAh, const __nv_bfloat16* pAl,
    const __nv_bfloat16* pBh, const __nv_bfloat16* pBl,
    long long aStep, long long bStep)
{
    cp_async16(sb + sdst0,                pAh + koff);
    cp_async16(sb + sdst0 + 4096,         pAh + aStep + koff);
    cp_async16(sb + 8192 + sdst0,         pAl + koff);
    cp_async16(sb + 8192 + sdst0 + 4096,  pAl + aStep + koff);
#pragma unroll
    for (int r = 0; r < 4; r++) {
        cp_async16(sb + 16384 + sdst0 + r * 4096, pBh + r * bStep + koff);
        cp_async16(sb + 32768 + sdst0 + r * 4096, pBl + r * bStep + koff);
    }
}

// C = alpha * A * B^T, fp32 out. A:[M,K] K-major (lda halves), B:[N,K] K-major (ldb).
// bgqa: B batch = (z>>5)*HKV + (z&31)/4.
__global__ __launch_bounds__(256, 1) void tc_gemm256(
    const __nv_bfloat16* __restrict__ Ah, const __nv_bfloat16* __restrict__ Al,
    const __nv_bfloat16* __restrict__ Bh, const __nv_bfloat16* __restrict__ Bl,
    float* __restrict__ Cf,
    int K, int lda, int ldb, int ldc,
    long long sA, long long sB, long long sC, float alpha, int bgqa)
{
    extern __shared__ uint32_t smw[];
    uint32_t asU = smem_to_u32(smw);

    int tid = threadIdx.x;
    int warp = tid >> 5;
    int lane = tid & 31;
    int warpM = warp & 1;      // M offset warpM*64
    int warpN = warp >> 1;     // N offset warpN*64
    int grp = lane >> 2;
    int thr = lane & 3;

    int z = blockIdx.z;
    long long aOff = (long long)z * sA;
    long long bOff = (bgqa ? (long long)((z >> 5) * HKV + ((z & 31) >> 2)) * sB
                           : (long long)z * sB);

    // ---- staging addresses ----
    int row0 = tid >> 2;               // 0..63
    int c16 = tid & 3;
    uint32_t sdst0 = (uint32_t)(row0 * 64 + ((c16 ^ ((row0 >> 1) & 3)) << 4));
    const __nv_bfloat16* pAh = Ah + aOff + (long long)(blockIdx.y * 128 + row0) * lda + c16 * 8;
    const __nv_bfloat16* pAl = Al + aOff + (long long)(blockIdx.y * 128 + row0) * lda + c16 * 8;
    const __nv_bfloat16* pBh = Bh + bOff + (long long)(blockIdx.x * 256 + row0) * ldb + c16 * 8;
    const __nv_bfloat16* pBl = Bl + bOff + (long long)(blockIdx.x * 256 + row0) * ldb + c16 * 8;
    long long aStep = 64LL * lda;
    long long bStep = 64LL * ldb;

    // ---- ldmatrix lane addresses ----
    // A x4 -> [m0-7 k0-7][m8-15 k0-7][m0-7 k8-15][m8-15 k8-15]
    uint32_t aRowL = (uint32_t)(warpM * 64 + (lane & 15));
    uint32_t aOffL = aRowL * 64 + ((((lane >> 4)) ^ ((aRowL >> 1) & 3)) << 4);
    // B x4 per 16-col group -> [n0-7 k0-7][n0-7 k8-15][n8-15 k0-7][n8-15 k8-15]
    uint32_t bCh = (lane >> 3) & 1;
    uint32_t bAddr[4];
#pragma unroll
    for (int np = 0; np < 4; np++) {
        uint32_t rowB = (uint32_t)(warpN * 64 + np * 16 + ((lane >> 4) << 3) + (lane & 7));
        bAddr[np] = 16384 + rowB * 64 + ((bCh ^ ((rowB >> 1) & 3)) << 4);
    }

    float acc[4][8][4];
#pragma unroll
    for (int mi = 0; mi < 4; mi++)
#pragma unroll
        for (int ni = 0; ni < 8; ni++)
#pragma unroll
            for (int r = 0; r < 4; r++) acc[mi][ni][r] = 0.0f;

    const int NC = K >> 5;

    // prologue: chunks 0,1
#pragma unroll
    for (int s = 0; s < 2; s++) {
        stage256(asU + s * STAGE256, s * 32, sdst0, pAh, pAl, pBh, pBl, aStep, bStep);
        cp_commit();
    }

    int stage = 0, wstage = 2;
    for (int kc = 0; kc < NC; kc++) {
        cp_wait<1>();
        __syncthreads();

        if (kc + 2 < NC)
            stage256(asU + wstage * STAGE256, (kc + 2) * 32, sdst0, pAh, pAl, pBh, pBl, aStep, bStep);
        cp_commit();

        uint32_t stb = asU + stage * STAGE256;

#pragma unroll
        for (int ks = 0; ks < 2; ks++) {
            uint32_t ksx = (uint32_t)(ks * 32);
            uint32_t ahf[16], alf[16];
#pragma unroll
            for (int mi = 0; mi < 4; mi++) {
                ldsm4(ahf + mi * 4, (stb + aOffL + mi * 1024) ^ ksx);
                ldsm4(alf + mi * 4, (stb + 8192 + aOffL + mi * 1024) ^ ksx);
            }
#pragma unroll
            for (int np = 0; np < 4; np++) {
                uint32_t bh4[4], bl4[4];
                ldsm4(bh4, (stb + bAddr[np]) ^ ksx);
                ldsm4(bl4, (stb + bAddr[np] + 16384) ^ ksx);
#pragma unroll
                for (int mi = 0; mi < 4; mi++) {
                    mma_bf16(acc[mi][2 * np],     ahf + mi * 4, bh4);       // hi*hi
                    mma_bf16(acc[mi][2 * np + 1], ahf + mi * 4, bh4 + 2);
                    mma_bf16(acc[mi][2 * np],     alf + mi * 4, bh4);       // lo*hi
                    mma_bf16(acc[mi][2 * np + 1], alf + mi * 4, bh4 + 2);
                    mma_bf16(acc[mi][2 * np],     ahf + mi * 4, bl4);       // hi*lo
                    mma_bf16(acc[mi][2 * np + 1], ahf + mi * 4, bl4 + 2);
                }
            }
        }
        stage = (stage == 2) ? 0 : stage + 1;
        wstage = (wstage == 2) ? 0 : wstage + 1;
    }

    // ---- epilogue (fp32) ----
    float* C = Cf + (long long)z * sC;
#pragma unroll
    for (int mi = 0; mi < 4; mi++) {
        int row = blockIdx.y * 128 + warpM * 64 + mi * 16 + grp;
#pragma unroll
        for (int ni = 0; ni < 8; ni++) {
            int col = blockIdx.x * 256 + warpN * 64 + ni * 8 + thr * 2;
            float2 v0 = make_float2(acc[mi][ni][0] * alpha, acc[mi][ni][1] * alpha);
            float2 v1 = make_float2(acc[mi][ni][2] * alpha, acc[mi][ni][3] * alpha);
            *(float2*)(C + (long long)row * ldc + col) = v0;
            *(float2*)(C + (long long)(row + 8) * ldc + col) = v1;
        }
    }
}

// ======================================================================================
// tc_gemm128: R12 kernel (128x128 tile, warp 64x32) — used for PV (N = HD = 128).
// ======================================================================================
#define STAGE_B 32768u
#define NSTAGE  3
static constexpr uint32_t SM_TOTAL128 = NSTAGE * STAGE_B;   // 98304

__global__ __launch_bounds__(256, 2) void tc_gemm128(
    const __nv_bfloat16* __restrict__ Ah, const __nv_bfloat16* __restrict__ Al,
    const __nv_bfloat16* __restrict__ Bh, const __nv_bfloat16* __restrict__ Bl,
    float* __restrict__ Cf, __nv_bfloat16* __restrict__ Ch, __nv_bfloat16* __restrict__ Cl,
    int K, int lda, int ldb, int ldc,
    long long sA, long long sB, long long sC, float alpha, int bgqa, int outmode)
{
    extern __shared__ uint32_t smw[];
    uint32_t asU = smem_to_u32(smw);

    int tid = threadIdx.x;
    int warp = tid >> 5;
    int lane = tid & 31;
    int warpM = warp & 1;
    int warpN = warp >> 1;
    int grp = lane >> 2;
    int thr = lane & 3;

    int z = blockIdx.z;
    long long aOff = (long long)z * sA;
    long long bOff = (bgqa ? (long long)((z >> 5) * HKV + ((z & 31) >> 2)) * sB
                           : (long long)z * sB);

    int row0 = tid >> 2;
    int c16 = tid & 3;
    uint32_t sdst0 = (uint32_t)(row0 * 64 + ((c16 ^ ((row0 >> 1) & 3)) * 16));
    const __nv_bfloat16* pAh = Ah + aOff + (long long)(blockIdx.y * 128 + row0) * lda + c16 * 8;
    const __nv_bfloat16* pAl = Al + aOff + (long long)(blockIdx.y * 128 + row0) * lda + c16 * 8;
    const __nv_bfloat16* pBh = Bh + bOff + (long long)(blockIdx.x * 128 + row0) * ldb + c16 * 8;
    const __nv_bfloat16* pBl = Bl + bOff + (long long)(blockIdx.x * 128 + row0) * ldb + c16 * 8;
    long long aStep = 64LL * lda;
    long long bStep = 64LL * ldb;

    uint32_t aRowL = (uint32_t)(warpM * 64 + (lane & 15));
    uint32_t aOffL = aRowL * 64 + (((lane >> 4) ^ (((lane & 15) >> 1) & 3)) * 16);
    uint32_t bRowL = (uint32_t)(warpN * 32 + ((lane >> 4) << 3) + (lane & 7));
    uint32_t bOffL = bRowL * 64 + (((((lane >> 3) & 1)) ^ (((lane & 7) >> 1) & 3)) * 16);

    float acc[4][4][4];
#pragma unroll
    for (int mi = 0; mi < 4; mi++)
#pragma unroll
        for (int ni = 0; ni < 4; ni++)
#pragma unroll
            for (int r = 0; r < 4; r++) acc[mi][ni][r] = 0.0f;

    const int NC = K >> 5;

#pragma unroll
    for (int s = 0; s < 2; s++) {
        uint32_t sb = asU + s * STAGE_B;
        int koff = s * 32;
        cp_async16(sb + sdst0,                 pAh + koff);
        cp_async16(sb + sdst0 + 4096,          pAh + aStep + koff);
        cp_async16(sb + 8192 + sdst0,          pAl + koff);
        cp_async16(sb + 8192 + sdst0 + 4096,   pAl + aStep + koff);
        cp_async16(sb + 16384 + sdst0,         pBh + koff);
        cp_async16(sb + 16384 + sdst0 + 4096,  pBh + bStep + koff);
        cp_async16(sb + 24576 + sdst0,         pBl + koff);
        cp_async16(sb + 24576 + sdst0 + 4096,  pBl + bStep + koff);
        cp_commit();
    }

    int stage = 0, wstage = 2;
    for (int kc = 0; kc < NC; kc++) {
        cp_wait<1>();
        __syncthreads();

        if (kc + 2 < NC) {
            uint32_t sb = asU + wstage * STAGE_B;
            int koff = (kc + 2) * 32;
            cp_async16(sb + sdst0,                 pAh + koff);
            cp_async16(sb + sdst0 + 4096,          pAh + aStep + koff);
            cp_async16(sb + 8192 + sdst0,          pAl + koff);
            cp_async16(sb + 8192 + sdst0 + 4096,   pAl + aStep + koff);
            cp_async16(sb + 16384 + sdst0,         pBh + koff);
            cp_async16(sb + 16384 + sdst0 + 4096,  pBh + bStep + koff);
            cp_async16(sb + 24576 + sdst0,         pBl + koff);
            cp_async16(sb + 24576 + sdst0 + 4096,  pBl + bStep + koff);
        }
        cp_commit();

        uint32_t stb = asU + stage * STAGE_B;
        uint32_t aB = stb + aOffL;
        uint32_t bB = stb + 16384 + bOffL;

#pragma unroll
        for (int ks = 0; ks < 2; ks++) {
            uint32_t ax = ks ? (aB ^ 32) : aB;
            uint32_t bx = ks ? (bB ^ 32) : bB;
            uint32_t bhf[8], blf[8];
            ldsm4(bhf,     bx);
            ldsm4(bhf + 4, bx + 1024);
            ldsm4(blf,     bx + 8192);
            ldsm4(blf + 4, bx + 8192 + 1024);
#pragma unroll
            for (int mi = 0; mi < 4; mi++) {
                uint32_t ahf[4], alf[4];
                ldsm4(ahf, ax + mi * 1024);
                ldsm4(alf, ax + 8192 + mi * 1024);
#pragma unroll
                for (int ni = 0; ni < 4; ni++)
                    mma_bf16(acc[mi][ni], ahf, bhf + ni * 2);
#pragma unroll
                for (int ni = 0; ni < 4; ni++)
                    mma_bf16(acc[mi][ni], alf, bhf + ni * 2);
#pragma unroll
                for (int ni = 0; ni < 4; ni++)
                    mma_bf16(acc[mi][ni], ahf, blf + ni * 2);
            }
        }
        stage = (stage == NSTAGE - 1) ? 0 : stage + 1;
        wstage = (wstage == NSTAGE - 1) ? 0 : wstage + 1;
    }

    if (outmode == 0) {
        float* C = Cf + (long long)z * sC;
#pragma unroll
        for (int mi = 0; mi < 4; mi++) {
            int row = blockIdx.y * 128 + warpM * 64 + mi * 16 + grp;
#pragma unroll
            for (int ni = 0; ni < 4; ni++) {
                int col = blockIdx.x * 128 + warpN * 32 + ni * 8 + thr * 2;
                float2 v0 = make_float2(acc[mi][ni][0] * alpha, acc[mi][ni][1] * alpha);
                float2 v1 = make_float2(acc[mi][ni][2] * alpha, acc[mi][ni][3] * alpha);
                *(float2*)(C + (long long)row * ldc + col) = v0;
                *(float2*)(C + (long long)(row + 8) * ldc + col) = v1;
            }
        }
    } else {
        long long base = (long long)(z >> 5) * SS * DD + (long long)(z & 31) * HD;
#pragma unroll
        for (int mi = 0; mi < 4; mi++) {
            int row = blockIdx.y * 128 + warpM * 64 + mi * 16 + grp;
#pragma unroll
            for (int ni = 0; ni < 4; ni++) {
                int col = blockIdx.x * 128 + warpN * 32 + ni * 8 + thr * 2;
#pragma unroll
                for (int half = 0; half < 2; half++) {
                    long long idx = base + (long long)(row + half * 8) * DD + col;
                    float v0 = acc[mi][ni][half * 2 + 0] * alpha;
                    float v1 = acc[mi][ni][half * 2 + 1] * alpha;
                    __nv_bfloat16 h0, l0, h1, l1;
                    split_bf16(v0, h0, l0);
                    split_bf16(v1, h1, l1);
                    __nv_bfloat162 hh; hh.x = h0; hh.y = h1;
                    __nv_bfloat162 ll; ll.x = l0; ll.y = l1;
                    *(__nv_bfloat162*)(Ch + idx) = hh;
                    *(__nv_bfloat162*)(Cl + idx) = ll;
                }
            }
        }
    }
}

// ---------------- fp32 -> bf16 hi/lo split (over float4) ----------------
__global__ __launch_bounds__(256) void split_kernel(
    const float* __restrict__ src, __nv_bfloat16* __restrict__ hi,
    __nv_bfloat16* __restrict__ lo, long long n4)
{
    long long i = (long long)blockIdx.x * 256 + threadIdx.x;
    if (i >= n4) return;
    float4 v = *(const float4*)(src + i * 4);
    __nv_bfloat16 h0, l0, h1, l1, h2, l2, h3, l3;
    split_bf16(v.x, h0, l0);
    split_bf16(v.y, h1, l1);
    split_bf16(v.z, h2, l2);
    split_bf16(v.w, h3, l3);
    __nv_bfloat162* hp = (__nv_bfloat162*)(hi + i * 4);
    __nv_bfloat162* lp = (__nv_bfloat162*)(lo + i * 4);
    __nv_bfloat162 a; a.x = h0; a.y = h1;
    __nv_bfloat162 b; b.x = h2; b.y = h3;
    __nv_bfloat162 c; c.x = l0; c.y = l1;
    __nv_bfloat162 d; d.x = l2; d.y = l3;
    hp[0] = a; hp[1] = b;
    lp[0] = c; lp[1] = d;
}

// ---------------- RoPE + RMSNorm + QKV split (writes hi/lo bf16) ----------------
__global__ __launch_bounds__(128) void rope_norm_kernel(
    const float* __restrict__ cosp, const float* __restrict__ sinp,
    const float* __restrict__ qw, const float* __restrict__ kw)
{
    int d = threadIdx.x;
    int hh = blockIdx.x;
    int s = blockIdx.y;
    int b = blockIdx.z;
    int kv = hh / 6;
    int slot = hh % 6;

    const float* row = g_qkv + ((size_t)(b * SS + s)) * QKVN + (size_t)hh * HD;
    float x = row[d];
    float out;

    __shared__ float red[HD];

    if (slot < 5) {
        float c = cosp[(size_t)s * HD + d];
        float sn = sinp[(size_t)s * HD + d];
        float other = row[d < 64 ? d + 64 : d - 64];
        float rot = (d < 64) ? -other : other;
        out = x * c + rot * sn;
        red[d] = out * out;
        __syncthreads();
#pragma unroll
        for (int off = 64; off > 0; off >>= 1) {
            if (d < off) red[d] += red[d + off];
            __syncthreads();
        }
        float inv = rsqrtf(red[0] / 128.0f + 1e-5f);
        const float* w = (slot < 4) ? qw : kw;
        out = w[d] * (out * inv);
    } else {
        out = x;  // v: plain copy
    }

    __nv_bfloat16 h, l;
    split_bf16(out, h, l);

    if (slot < 4) {
        int hq = kv * 4 + slot;
        size_t idx = (((size_t)(b * NH + hq)) * SS + s) * HD + d;
        g_qh[idx] = h; g_ql[idx] = l;
    } else if (slot == 4) {
        size_t idx = (((size_t)(b * HKV + kv)) * SS + s) * HD + d;
        g_kh[idx] = h; g_kl[idx] = l;
    } else {
        size_t idx = (((size_t)(b * HKV + kv)) * HD + d) * SS + s;   // transposed
        g_vth[idx] = h; g_vtl[idx] = l;
    }
}

// ---------------- row softmax over S=2048 -> bf16 hi/lo probs ----------------
__global__ __launch_bounds__(256) void softmax_kernel()
{
    size_t rowIdx = blockIdx.x;
    const float* x = g_scores + rowIdx * (size_t)SS;
    __nv_bfloat16* ph = g_ph + rowIdx * (size_t)SS;
    __nv_bfloat16* pl = g_pl + rowIdx * (size_t)SS;
    int t = threadIdx.x;

    float v[8];
    float m = -INFINITY;
#pragma unroll
    for (int i = 0; i < 8; i++) {
        v[i] = x[t + i * 256];
        m = fmaxf(m, v[i]);
    }

    __shared__ float red[256];
    red[t] = m;
    __syncthreads();
#pragma unroll
    for (int off = 128; off > 0; off >>= 1) {
        if (t < off) red[t] = fmaxf(red[t], red[t + off]);
        __syncthreads();
    }
    m = red[0];
    __syncthreads();

    float sum = 0.0f;
#pragma unroll
    for (int i = 0; i < 8; i++) {
        v[i] = expf(v[i] - m);
        sum += v[i];
    }
    red[t] = sum;
    __syncthreads();
#pragma unroll
    for (int off = 128; off > 0; off >>= 1) {
        if (t < off) red[t] += red[t + off];
        __syncthreads();
    }
    float inv = 1.0f / red[0];
#pragma unroll
    for (int i = 0; i < 8; i++) {
        float p = v[i] * inv;
        __nv_bfloat16 h, l;
        split_bf16(p, h, l);
        ph[t + i * 256] = h;
        pl[t + i * 256] = l;
    }
}

// ---------------- launcher ----------------
extern "C" void kernel_launch(void* const* d_in, const int* in_sizes, int n_in,
                              void* d_out, int out_size)
{
    (void)in_sizes; (void)n_in; (void)out_size;
    const float* hidden = (const float*)d_in[0];  // [B,S,D]
    const float* cosp   = (const float*)d_in[1];  // [1,S,128]
    const float* sinp   = (const float*)d_in[2];  // [1,S,128]
    const float* w_qkv  = (const float*)d_in[3];  // [6144,4096]
    const float* w_o    = (const float*)d_in[4];  // [4096,4096]
    const float* qnw    = (const float*)d_in[5];  // [128]
    const float* knw    = (const float*)d_in[6];  // [128]
    float* out = (float*)d_out;                   // [B,S,D]

    float *p_qkv, *p_sc;
    __nv_bfloat16 *p_hh, *p_hl, *p_wqh, *p_wql, *p_woh, *p_wol;
    __nv_bfloat16 *p_qhh, *p_qll, *p_kh, *p_kl, *p_vth, *p_vtl, *p_ph, *p_pl, *p_ah, *p_al;
    cudaGetSymbolAddress((void**)&p_qkv, g_qkv);
    cudaGetSymbolAddress((void**)&p_sc,  g_scores);
    cudaGetSymbolAddress((void**)&p_hh,  g_hh);
    cudaGetSymbolAddress((void**)&p_hl,  g_hl);
    cudaGetSymbolAddress((void**)&p_wqh, g_wqh);
    cudaGetSymbolAddress((void**)&p_wql, g_wql);
    cudaGetSymbolAddress((void**)&p_woh, g_woh);
    cudaGetSymbolAddress((void**)&p_wol, g_wol);
    cudaGetSymbolAddress((void**)&p_qhh, g_qh);
    cudaGetSymbolAddress((void**)&p_qll, g_ql);
    cudaGetSymbolAddress((void**)&p_kh,  g_kh);
    cudaGetSymbolAddress((void**)&p_kl,  g_kl);
    cudaGetSymbolAddress((void**)&p_vth, g_vth);
    cudaGetSymbolAddress((void**)&p_vtl, g_vtl);
    cudaGetSymbolAddress((void**)&p_ph,  g_ph);
    cudaGetSymbolAddress((void**)&p_pl,  g_pl);
    cudaGetSymbolAddress((void**)&p_ah,  g_ah);
    cudaGetSymbolAddress((void**)&p_al,  g_al);

    cudaFuncSetAttribute(tc_gemm256, cudaFuncAttributeMaxDynamicSharedMemorySize, SM_TOTAL256);
    cudaFuncSetAttribute(tc_gemm128, cudaFuncAttributeMaxDynamicSharedMemorySize, SM_TOTAL128);

    const float scale = 0.08838834764831843f;  // 1/sqrt(128)

    // 0) split fp32 inputs into bf16 hi/lo
    long long nh4 = (long long)BB * SS * DD / 4;
    long long nq4 = (long long)QKVN * DD / 4;
    long long no4 = (long long)DD * DD / 4;
    split_kernel<<<(unsigned)((nh4 + 255) / 256), 256>>>(hidden, p_hh, p_hl, nh4);
    split_kernel<<<(unsigned)((nq4 + 255) / 256), 256>>>(w_qkv, p_wqh, p_wql, nq4);
    split_kernel<<<(unsigned)((no4 + 255) / 256), 256>>>(w_o, p_woh, p_wol, no4);

    // 1) qkv = hidden @ w_qkv^T   [4096, 6144] fp32
    tc_gemm256<<<dim3(QKVN / 256, (BB * SS) / 128, 1), 256, SM_TOTAL256>>>(
        p_hh, p_hl, p_wqh, p_wql, p_qkv,
        DD, DD, DD, QKVN, 0, 0, 0, 1.0f, 0);

    // 2) RoPE + RMSNorm + split (q/k/vt hi+lo)
    rope_norm_kernel<<<dim3(HKV * 6, SS, BB), 128>>>(cosp, sinp, qnw, knw);

    // 3) scores = scale * Q @ K^T (fp32), batched z = b*32+h, GQA K
    tc_gemm256<<<dim3(SS / 256, SS / 128, BB * NH), 256, SM_TOTAL256>>>(
        p_qhh, p_qll, p_kh, p_kl, p_sc,
        HD, HD, HD, SS,
        (long long)SS * HD, (long long)SS * HD, (long long)SS * SS,
        scale, 1);

    // 4) softmax -> P hi/lo bf16
    softmax_kernel<<<dim3(BB * NH * SS), 256>>>();

    // 5) attn = P @ Vt^T -> bf16 hi/lo at [B,S,32,HD]
    tc_gemm128<<<dim3(1, SS / 128, BB * NH), 256, SM_TOTAL128>>>(
        p_ph, p_pl, p_vth, p_vtl, nullptr, p_ah, p_al,
        SS, SS, SS, DD,
        (long long)SS * SS, (long long)HD * SS, 0,
        1.0f, 1, 1);

    // 6) out = attn @ w_o^T (fp32)
    tc_gemm256<<<dim3(DD / 256, (BB * SS) / 128, 1), 256, SM_TOTAL256>>>(
        p_ah, p_al, p_woh, p_wol, out,
        DD, DD, DD, DD, 0, 0, 0, 1.0f, 0);
}

// round 15
// speedup vs baseline: 1.1691x; 1.1691x over previous
#include <cuda_runtime.h>
#include <cuda_bf16.h>
#include <math.h>
#include <cstdint>

#define BB 2
#define SS 2048
#define DD 4096
#define QKVN 6144
#define HKV 8
#define NH 32
#define HD 128

// ---------------- scratch (static device globals; no runtime allocation) ----------------
__device__ float g_qkv[(size_t)BB * SS * QKVN];            // fp32, feeds rope
__device__ float g_scores[(size_t)BB * NH * SS * SS];      // fp32 scaled logits
__device__ float2 g_stats[(size_t)BB * NH * SS];           // per row: {max, 1/sumexp}
// hi/lo bf16 operand arrays
__device__ __nv_bfloat16 g_hh[(size_t)BB * SS * DD];
__device__ __nv_bfloat16 g_hl[(size_t)BB * SS * DD];
__device__ __nv_bfloat16 g_wqh[(size_t)QKVN * DD];
__device__ __nv_bfloat16 g_wql[(size_t)QKVN * DD];
__device__ __nv_bfloat16 g_woh[(size_t)DD * DD];
__device__ __nv_bfloat16 g_wol[(size_t)DD * DD];
__device__ __nv_bfloat16 g_qh[(size_t)BB * NH * SS * HD];
__device__ __nv_bfloat16 g_ql[(size_t)BB * NH * SS * HD];
__device__ __nv_bfloat16 g_kh[(size_t)BB * HKV * SS * HD];
__device__ __nv_bfloat16 g_kl[(size_t)BB * HKV * SS * HD];
__device__ __nv_bfloat16 g_vth[(size_t)BB * HKV * HD * SS];   // V transposed [b,kv,d,s]
__device__ __nv_bfloat16 g_vtl[(size_t)BB * HKV * HD * SS];
__device__ __nv_bfloat16 g_ah[(size_t)BB * SS * DD];          // attn out hi [B,S,32,HD]
__device__ __nv_bfloat16 g_al[(size_t)BB * SS * DD];          // attn out lo

// ================= helpers =================
__device__ __forceinline__ uint32_t smem_to_u32(const void* smem_ptr) {
    uint32_t addr;
    asm("{ .reg .u64 tmp; cvta.to.shared.u64 tmp, %1; cvt.u32.u64 %0, tmp; }"
        : "=r"(addr) : "l"(smem_ptr));
    return addr;
}

__device__ __forceinline__ void cp_async16(uint32_t saddr, const void* gptr) {
    asm volatile("cp.async.cg.shared.global [%0], [%1], 16;" :: "r"(saddr), "l"(gptr));
}
__device__ __forceinline__ void cp_commit() {
    asm volatile("cp.async.commit_group;" ::: "memory");
}
template <int N>
__device__ __forceinline__ void cp_wait() {
    asm volatile("cp.async.wait_group %0;" :: "n"(N) : "memory");
}

__device__ __forceinline__ void ldsm4(uint32_t* r, uint32_t addr) {
    asm volatile("ldmatrix.sync.aligned.m8n8.x4.shared.b16 {%0,%1,%2,%3}, [%4];"
        : "=r"(r[0]), "=r"(r[1]), "=r"(r[2]), "=r"(r[3]) : "r"(addr));
}

__device__ __forceinline__ void mma_bf16(float* d, const uint32_t* a, const uint32_t* b) {
    asm volatile(
        "mma.sync.aligned.m16n8k16.row.col.f32.bf16.bf16.f32 "
        "{%0,%1,%2,%3}, {%4,%5,%6,%7}, {%8,%9}, {%0,%1,%2,%3};"
        : "+f"(d[0]), "+f"(d[1]), "+f"(d[2]), "+f"(d[3])
        : "r"(a[0]), "r"(a[1]), "r"(a[2]), "r"(a[3]),
          "r"(b[0]), "r"(b[1]));
}

__device__ __forceinline__ void split_bf16(float v, __nv_bfloat16& h, __nv_bfloat16& l) {
    h = __float2bfloat16(v);
    l = __float2bfloat16(v - __bfloat162float(h));
}

__device__ __forceinline__ uint32_t pack_bf2(__nv_bfloat16 a, __nv_bfloat16 b) {
    __nv_bfloat162 t; t.x = a; t.y = b;
    return *(uint32_t*)&t;
}

#define LOG2E 1.4426950408889634f

// ======================================================================================
// tc_gemm128 (R12): 128x128 tile, warp 64x32, 3-stage, 2 CTAs/SM. C = alpha*A*B^T fp32.
// ======================================================================================
#define STAGE_B 32768u
#define NSTAGE  3
static constexpr uint32_t SM_TOTAL128 = NSTAGE * STAGE_B;   // 98304

__global__ __launch_bounds__(256, 2) void tc_gemm128(
    const __nv_bfloat16* __restrict__ Ah, const __nv_bfloat16* __restrict__ Al,
    const __nv_bfloat16* __restrict__ Bh, const __nv_bfloat16* __restrict__ Bl,
    float* __restrict__ Cf,
    int K, int lda, int ldb, int ldc,
    long long sA, long long sB, long long sC, float alpha, int bgqa)
{
    extern __shared__ uint32_t smw[];
    uint32_t asU = smem_to_u32(smw);

    int tid = threadIdx.x;
    int warp = tid >> 5;
    int lane = tid & 31;
    int warpM = warp & 1;
    int warpN = warp >> 1;
    int grp = lane >> 2;
    int thr = lane & 3;

    int z = blockIdx.z;
    long long aOff = (long long)z * sA;
    long long bOff = (bgqa ? (long long)((z >> 5) * HKV + ((z & 31) >> 2)) * sB
                           : (long long)z * sB);

    int row0 = tid >> 2;
    int c16 = tid & 3;
    uint32_t sdst0 = (uint32_t)(row0 * 64 + ((c16 ^ ((row0 >> 1) & 3)) * 16));
    const __nv_bfloat16* pAh = Ah + aOff + (long long)(blockIdx.y * 128 + row0) * lda + c16 * 8;
    const __nv_bfloat16* pAl = Al + aOff + (long long)(blockIdx.y * 128 + row0) * lda + c16 * 8;
    const __nv_bfloat16* pBh = Bh + bOff + (long long)(blockIdx.x * 128 + row0) * ldb + c16 * 8;
    const __nv_bfloat16* pBl = Bl + bOff + (long long)(blockIdx.x * 128 + row0) * ldb + c16 * 8;
    long long aStep = 64LL * lda;
    long long bStep = 64LL * ldb;

    uint32_t aRowL = (uint32_t)(warpM * 64 + (lane & 15));
    uint32_t aOffL = aRowL * 64 + (((lane >> 4) ^ (((lane & 15) >> 1) & 3)) * 16);
    uint32_t bRowL = (uint32_t)(warpN * 32 + ((lane >> 4) << 3) + (lane & 7));
    uint32_t bOffL = bRowL * 64 + (((((lane >> 3) & 1)) ^ (((lane & 7) >> 1) & 3)) * 16);

    float acc[4][4][4];
#pragma unroll
    for (int mi = 0; mi < 4; mi++)
#pragma unroll
        for (int ni = 0; ni < 4; ni++)
#pragma unroll
            for (int r = 0; r < 4; r++) acc[mi][ni][r] = 0.0f;

    const int NC = K >> 5;

#pragma unroll
    for (int s = 0; s < 2; s++) {
        uint32_t sb = asU + s * STAGE_B;
        int koff = s * 32;
        cp_async16(sb + sdst0,                 pAh + koff);
        cp_async16(sb + sdst0 + 4096,          pAh + aStep + koff);
        cp_async16(sb + 8192 + sdst0,          pAl + koff);
        cp_async16(sb + 8192 + sdst0 + 4096,   pAl + aStep + koff);
        cp_async16(sb + 16384 + sdst0,         pBh + koff);
        cp_async16(sb + 16384 + sdst0 + 4096,  pBh + bStep + koff);
        cp_async16(sb + 24576 + sdst0,         pBl + koff);
        cp_async16(sb + 24576 + sdst0 + 4096,  pBl + bStep + koff);
        cp_commit();
    }

    int stage = 0, wstage = 2;
    for (int kc = 0; kc < NC; kc++) {
        cp_wait<1>();
        __syncthreads();

        if (kc + 2 < NC) {
            uint32_t sb = asU + wstage * STAGE_B;
            int koff = (kc + 2) * 32;
            cp_async16(sb + sdst0,                 pAh + koff);
            cp_async16(sb + sdst0 + 4096,          pAh + aStep + koff);
            cp_async16(sb + 8192 + sdst0,          pAl + koff);
            cp_async16(sb + 8192 + sdst0 + 4096,   pAl + aStep + koff);
            cp_async16(sb + 16384 + sdst0,         pBh + koff);
            cp_async16(sb + 16384 + sdst0 + 4096,  pBh + bStep + koff);
            cp_async16(sb + 24576 + sdst0,         pBl + koff);
            cp_async16(sb + 24576 + sdst0 + 4096,  pBl + bStep + koff);
        }
        cp_commit();

        uint32_t stb = asU + stage * STAGE_B;
        uint32_t aB = stb + aOffL;
        uint32_t bB = stb + 16384 + bOffL;

#pragma unroll
        for (int ks = 0; ks < 2; ks++) {
            uint32_t ax = ks ? (aB ^ 32) : aB;
            uint32_t bx = ks ? (bB ^ 32) : bB;
            uint32_t bhf[8], blf[8];
            ldsm4(bhf,     bx);
            ldsm4(bhf + 4, bx + 1024);
            ldsm4(blf,     bx + 8192);
            ldsm4(blf + 4, bx + 8192 + 1024);
#pragma unroll
            for (int mi = 0; mi < 4; mi++) {
                uint32_t ahf[4], alf[4];
                ldsm4(ahf, ax + mi * 1024);
                ldsm4(alf, ax + 8192 + mi * 1024);
#pragma unroll
                for (int ni = 0; ni < 4; ni++)
                    mma_bf16(acc[mi][ni], ahf, bhf + ni * 2);
#pragma unroll
                for (int ni = 0; ni < 4; ni++)
                    mma_bf16(acc[mi][ni], alf, bhf + ni * 2);
#pragma unroll
                for (int ni = 0; ni < 4; ni++)
                    mma_bf16(acc[mi][ni], ahf, blf + ni * 2);
            }
        }
        stage = (stage == NSTAGE - 1) ? 0 : stage + 1;
        wstage = (wstage == NSTAGE - 1) ? 0 : wstage + 1;
    }

    float* C = Cf + (long long)z * sC;
#pragma unroll
    for (int mi = 0; mi < 4; mi++) {
        int row = blockIdx.y * 128 + warpM * 64 + mi * 16 + grp;
#pragma unroll
        for (int ni = 0; ni < 4; ni++) {
            int col = blockIdx.x * 128 + warpN * 32 + ni * 8 + thr * 2;
            float2 v0 = make_float2(acc[mi][ni][0] * alpha, acc[mi][ni][1] * alpha);
            float2 v1 = make_float2(acc[mi][ni][2] * alpha, acc[mi][ni][3] * alpha);
            *(float2*)(C + (long long)row * ldc + col) = v0;
            *(float2*)(C + (long long)(row + 8) * ldc + col) = v1;
        }
    }
}

// ======================================================================================
// tc_gemm_pv: PV GEMM with fused softmax-normalization in A-staging.
// A = exp(scores - m)*invl, split hi/lo on the fly. Shapes hardcoded:
// M=128 q-rows (blockIdx.y), N=HD=128, K=SS=2048 keys, batch z = b*32+h (blockIdx.z).
// Smem: raw fp32 ring 2x16K @0 | bf16 A ring 2x(8K hi+8K lo) @32K | B ring 3x16K @64K.
// ======================================================================================
static constexpr uint32_t SM_TOTAL_PV = 114688u;   // 112 KB

__global__ __launch_bounds__(256, 2) void tc_gemm_pv(
    const float* __restrict__ S, const float2* __restrict__ stats,
    const __nv_bfloat16* __restrict__ Bh, const __nv_bfloat16* __restrict__ Bl,
    __nv_bfloat16* __restrict__ Ch, __nv_bfloat16* __restrict__ Cl)
{
    extern __shared__ char smc[];
    uint32_t asU = smem_to_u32(smc);

    int tid = threadIdx.x;
    int warp = tid >> 5;
    int lane = tid & 31;
    int warpM = warp & 1;
    int warpN = warp >> 1;
    int grp = lane >> 2;
    int thr = lane & 3;

    int z = blockIdx.z;
    int by = blockIdx.y;
    long long aOff = (long long)z * SS * SS;
    long long bOff = (long long)((z >> 5) * HKV + ((z & 31) >> 2)) * HD * SS;

    // ---- raw A staging (fp32 scores): 4 pieces/thread/chunk ----
    int rrow = tid >> 3;               // 0..31 (+32j)
    int rc16 = tid & 7;                // float4 index in 128B row
    const float* pS = S + aOff + (long long)(by * 128 + rrow) * SS + rc16 * 4;
    uint32_t rdst = (uint32_t)(rrow * 128 + rc16 * 16);

    // per-thread row stats (rows rrow+32j)
    float mr[4], il[4];
#pragma unroll
    for (int j = 0; j < 4; j++) {
        float2 st = stats[(size_t)z * SS + by * 128 + rrow + 32 * j];
        mr[j] = st.x; il[j] = st.y;
    }

    // ---- B staging (Vt hi/lo): rows = HD ----
    int row0 = tid >> 2;               // 0..63
    int c16 = tid & 3;
    uint32_t sdst0 = (uint32_t)(row0 * 64 + ((c16 ^ ((row0 >> 1) & 3)) * 16));
    const __nv_bfloat16* pBh = Bh + bOff + (long long)row0 * SS + c16 * 8;
    const __nv_bfloat16* pBl = Bl + bOff + (long long)row0 * SS + c16 * 8;
    long long bStep = 64LL * SS;

    // ---- ldmatrix lane addresses (tile-local) ----
    uint32_t aRowL = (uint32_t)(warpM * 64 + (lane & 15));
    uint32_t aOffL = aRowL * 64 + (((lane >> 4) ^ (((lane & 15) >> 1) & 3)) * 16);
    uint32_t bRowL = (uint32_t)(warpN * 32 + ((lane >> 4) << 3) + (lane & 7));
    uint32_t bOffL = bRowL * 64 + (((((lane >> 3) & 1)) ^ (((lane & 7) >> 1) & 3)) * 16);

    float acc[4][4][4];
#pragma unroll
    for (int mi = 0; mi < 4; mi++)
#pragma unroll
        for (int ni = 0; ni < 4; ni++)
#pragma unroll
            for (int r = 0; r < 4; r++) acc[mi][ni][r] = 0.0f;

    const int NC = SS >> 5;    // 64

    // stage chunk cc: raw -> slot cc&1, B -> slot cc%3
#define PV_STAGE(cc) do { \
        uint32_t rb = asU + (uint32_t)(((cc) & 1) << 14); \
        uint32_t bb = asU + 65536u + (uint32_t)(((cc) % 3) * 16384); \
        int koff = (cc) * 32; \
        cp_async16(rb + rdst,          pS + koff); \
        cp_async16(rb + rdst + 4096,   pS + 32LL * SS + koff); \
        cp_async16(rb + rdst + 8192,   pS + 64LL * SS + koff); \
        cp_async16(rb + rdst + 12288,  pS + 96LL * SS + koff); \
        cp_async16(bb + sdst0,         pBh + koff); \
        cp_async16(bb + sdst0 + 4096,  pBh + bStep + koff); \
        cp_async16(bb + 8192 + sdst0,        pBl + koff); \
        cp_async16(bb + 8192 + sdst0 + 4096, pBl + bStep + koff); \
    } while (0)

    // convert chunk cc (self-staged raw pieces) -> bf16 A slot cc&1
#define PV_CONVERT(cc) do { \
        uint32_t rb = asU + (uint32_t)(((cc) & 1) << 14); \
        uint32_t db = asU + 32768u + (uint32_t)(((cc) & 1) << 14); \
        _Pragma("unroll") \
        for (int j = 0; j < 4; j++) { \
            float4 s4 = *(const float4*)(smc + (rb - asU) + rdst + j * 4096); \
            float p0 = exp2f((s4.x - mr[j]) * LOG2E) * il[j]; \
            float p1 = exp2f((s4.y - mr[j]) * LOG2E) * il[j]; \
            float p2 = exp2f((s4.z - mr[j]) * LOG2E) * il[j]; \
            float p3 = exp2f((s4.w - mr[j]) * LOG2E) * il[j]; \
            __nv_bfloat16 h0, l0, h1, l1, h2, l2, h3, l3; \
            split_bf16(p0, h0, l0); split_bf16(p1, h1, l1); \
            split_bf16(p2, h2, l2); split_bf16(p3, h3, l3); \
            int rw = rrow + 32 * j; \
            uint32_t doff = (uint32_t)(rw * 64 + (((rc16 >> 1) ^ ((rw >> 1) & 3)) << 4) + (rc16 & 1) * 8); \
            *(uint2*)(smc + (db - asU) + doff)        = make_uint2(pack_bf2(h0, h1), pack_bf2(h2, h3)); \
            *(uint2*)(smc + (db - asU) + 8192 + doff) = make_uint2(pack_bf2(l0, l1), pack_bf2(l2, l3)); \
        } \
    } while (0)

    // prologue: chunks 0,1 staged; convert chunk 0
    PV_STAGE(0); cp_commit();
    PV_STAGE(1); cp_commit();
    cp_wait<1>();
    PV_CONVERT(0);

    for (int kc = 0; kc < NC; kc++) {
        __syncthreads();   // bf16 slot kc&1 + B slot reuse safety
        if (kc + 2 < NC) PV_STAGE(kc + 2);
        cp_commit();
        if (kc + 1 < NC) {
            cp_wait<1>();          // group kc+1 (raw+B) complete
            PV_CONVERT(kc + 1);    // self-staged: no barrier needed before reading raw
        } else {
            cp_wait<0>();
        }

        uint32_t aT = asU + 32768u + (uint32_t)((kc & 1) << 14);
        uint32_t bT = asU + 65536u + (uint32_t)((kc % 3) * 16384);
        uint32_t aB = aT + aOffL;
        uint32_t bB = bT + bOffL;

#pragma unroll
        for (int ks = 0; ks < 2; ks++) {
            uint32_t ax = ks ? (aB ^ 32) : aB;
            uint32_t bx = ks ? (bB ^ 32) : bB;
            uint32_t bhf[8], blf[8];
            ldsm4(bhf,     bx);
            ldsm4(bhf + 4, bx + 1024);
            ldsm4(blf,     bx + 8192);
            ldsm4(blf + 4, bx + 8192 + 1024);
#pragma unroll
            for (int mi = 0; mi < 4; mi++) {
                uint32_t ahf[4], alf[4];
                ldsm4(ahf, ax + mi * 1024);
                ldsm4(alf, ax + 8192 + mi * 1024);
#pragma unroll
                for (int ni = 0; ni < 4; ni++)
                    mma_bf16(acc[mi][ni], ahf, bhf + ni * 2);
#pragma unroll
                for (int ni = 0; ni < 4; ni++)
                    mma_bf16(acc[mi][ni], alf, bhf + ni * 2);
#pragma unroll
                for (int ni = 0; ni < 4; ni++)
                    mma_bf16(acc[mi][ni], ahf, blf + ni * 2);
            }
        }
    }

    // ---- epilogue: bf16 hi/lo attn at [B,S,32,HD] ----
    long long base = (long long)(z >> 5) * SS * DD + (long long)(z & 31) * HD;
#pragma unroll
    for (int mi = 0; mi < 4; mi++) {
        int row = by * 128 + warpM * 64 + mi * 16 + grp;
#pragma unroll
        for (int ni = 0; ni < 4; ni++) {
            int col = warpN * 32 + ni * 8 + thr * 2;
#pragma unroll
            for (int half = 0; half < 2; half++) {
                long long idx = base + (long long)(row + half * 8) * DD + col;
                __nv_bfloat16 h0, l0, h1, l1;
                split_bf16(acc[mi][ni][half * 2 + 0], h0, l0);
                split_bf16(acc[mi][ni][half * 2 + 1], h1, l1);
                *(uint32_t*)(Ch + idx) = pack_bf2(h0, h1);
                *(uint32_t*)(Cl + idx) = pack_bf2(l0, l1);
            }
        }
    }
}

// ---------------- fp32 -> bf16 hi/lo split (over float4) ----------------
__global__ __launch_bounds__(256) void split_kernel(
    const float* __restrict__ src, __nv_bfloat16* __restrict__ hi,
    __nv_bfloat16* __restrict__ lo, long long n4)
{
    long long i = (long long)blockIdx.x * 256 + threadIdx.x;
    if (i >= n4) return;
    float4 v = *(const float4*)(src + i * 4);
    __nv_bfloat16 h0, l0, h1, l1, h2, l2, h3, l3;
    split_bf16(v.x, h0, l0);
    split_bf16(v.y, h1, l1);
    split_bf16(v.z, h2, l2);
    split_bf16(v.w, h3, l3);
    uint2* hp = (uint2*)(hi + i * 4);
    uint2* lp = (uint2*)(lo + i * 4);
    *hp = make_uint2(pack_bf2(h0, h1), pack_bf2(h2, h3));
    *lp = make_uint2(pack_bf2(l0, l1), pack_bf2(l2, l3));
}

// ---------------- RoPE + RMSNorm + QKV split (writes hi/lo bf16) ----------------
__global__ __launch_bounds__(128) void rope_norm_kernel(
    const float* __restrict__ cosp, const float* __restrict__ sinp,
    const float* __restrict__ qw, const float* __restrict__ kw)
{
    int d = threadIdx.x;
    int hh = blockIdx.x;
    int s = blockIdx.y;
    int b = blockIdx.z;
    int kv = hh / 6;
    int slot = hh % 6;

    const float* row = g_qkv + ((size_t)(b * SS + s)) * QKVN + (size_t)hh * HD;
    float x = row[d];
    float out;

    __shared__ float red[HD];

    if (slot < 5) {
        float c = cosp[(size_t)s * HD + d];
        float sn = sinp[(size_t)s * HD + d];
        float other = row[d < 64 ? d + 64 : d - 64];
        float rot = (d < 64) ? -other : other;
        out = x * c + rot * sn;
        red[d] = out * out;
        __syncthreads();
#pragma unroll
        for (int off = 64; off > 0; off >>= 1) {
            if (d < off) red[d] += red[d + off];
            __syncthreads();
        }
        float inv = rsqrtf(red[0] / 128.0f + 1e-5f);
        const float* w = (slot < 4) ? qw : kw;
        out = w[d] * (out * inv);
    } else {
        out = x;  // v: plain copy
    }

    __nv_bfloat16 h, l;
    split_bf16(out, h, l);

    if (slot < 4) {
        int hq = kv * 4 + slot;
        size_t idx = (((size_t)(b * NH + hq)) * SS + s) * HD + d;
        g_qh[idx] = h; g_ql[idx] = l;
    } else if (slot == 4) {
        size_t idx = (((size_t)(b * HKV + kv)) * SS + s) * HD + d;
        g_kh[idx] = h; g_kl[idx] = l;
    } else {
        size_t idx = (((size_t)(b * HKV + kv)) * HD + d) * SS + s;   // transposed
        g_vth[idx] = h; g_vtl[idx] = l;
    }
}

// ---------------- per-row stats: m = max, invl = 1/sum exp(s-m) ----------------
__global__ __launch_bounds__(256) void stats_kernel()
{
    size_t rowIdx = blockIdx.x;
    const float4* x = (const float4*)(g_scores + rowIdx * (size_t)SS);
    int t = threadIdx.x;

    float4 a = x[t];
    float4 b = x[t + 256];
    float m = fmaxf(fmaxf(fmaxf(a.x, a.y), fmaxf(a.z, a.w)),
                    fmaxf(fmaxf(b.x, b.y), fmaxf(b.z, b.w)));

    __shared__ float red[256];
    red[t] = m;
    __syncthreads();
#pragma unroll
    for (int off = 128; off > 0; off >>= 1) {
        if (t < off) red[t] = fmaxf(red[t], red[t + off]);
        __syncthreads();
    }
    m = red[0];
    __syncthreads();

    float sum = exp2f((a.x - m) * LOG2E) + exp2f((a.y - m) * LOG2E)
              + exp2f((a.z - m) * LOG2E) + exp2f((a.w - m) * LOG2E)
              + exp2f((b.x - m) * LOG2E) + exp2f((b.y - m) * LOG2E)
              + exp2f((b.z - m) * LOG2E) + exp2f((b.w - m) * LOG2E);
    red[t] = sum;
    __syncthreads();
#pragma unroll
    for (int off = 128; off > 0; off >>= 1) {
        if (t < off) red[t] += red[t + off];
        __syncthreads();
    }
    if (t == 0)
        g_stats[rowIdx] = make_float2(m, 1.0f / red[0]);
}

// ---------------- launcher ----------------
extern "C" void kernel_launch(void* const* d_in, const int* in_sizes, int n_in,
                              void* d_out, int out_size)
{
    (void)in_sizes; (void)n_in; (void)out_size;
    const float* hidden = (const float*)d_in[0];  // [B,S,D]
    const float* cosp   = (const float*)d_in[1];  // [1,S,128]
    const float* sinp   = (const float*)d_in[2];  // [1,S,128]
    const float* w_qkv  = (const float*)d_in[3];  // [6144,4096]
    const float* w_o    = (const float*)d_in[4];  // [4096,4096]
    const float* qnw    = (const float*)d_in[5];  // [128]
    const float* knw    = (const float*)d_in[6];  // [128]
    float* out = (float*)d_out;                   // [B,S,D]

    float *p_qkv, *p_sc;
    float2* p_st;
    __nv_bfloat16 *p_hh, *p_hl, *p_wqh, *p_wql, *p_woh, *p_wol;
    __nv_bfloat16 *p_qhh, *p_qll, *p_kh, *p_kl, *p_vth, *p_vtl, *p_ah, *p_al;
    cudaGetSymbolAddress((void**)&p_qkv, g_qkv);
    cudaGetSymbolAddress((void**)&p_sc,  g_scores);
    cudaGetSymbolAddress((void**)&p_st,  g_stats);
    cudaGetSymbolAddress((void**)&p_hh,  g_hh);
    cudaGetSymbolAddress((void**)&p_hl,  g_hl);
    cudaGetSymbolAddress((void**)&p_wqh, g_wqh);
    cudaGetSymbolAddress((void**)&p_wql, g_wql);
    cudaGetSymbolAddress((void**)&p_woh, g_woh);
    cudaGetSymbolAddress((void**)&p_wol, g_wol);
    cudaGetSymbolAddress((void**)&p_qhh, g_qh);
    cudaGetSymbolAddress((void**)&p_qll, g_ql);
    cudaGetSymbolAddress((void**)&p_kh,  g_kh);
    cudaGetSymbolAddress((void**)&p_kl,  g_kl);
    cudaGetSymbolAddress((void**)&p_vth, g_vth);
    cudaGetSymbolAddress((void**)&p_vtl, g_vtl);
    cudaGetSymbolAddress((void**)&p_ah,  g_ah);
    cudaGetSymbolAddress((void**)&p_al,  g_al);

    cudaFuncSetAttribute(tc_gemm128, cudaFuncAttributeMaxDynamicSharedMemorySize, SM_TOTAL128);
    cudaFuncSetAttribute(tc_gemm_pv, cudaFuncAttributeMaxDynamicSharedMemorySize, SM_TOTAL_PV);

    const float scale = 0.08838834764831843f;  // 1/sqrt(128)

    // 0) split fp32 inputs into bf16 hi/lo
    long long nh4 = (long long)BB * SS * DD / 4;
    long long nq4 = (long long)QKVN * DD / 4;
    long long no4 = (long long)DD * DD / 4;
    split_kernel<<<(unsigned)((nh4 + 255) / 256), 256>>>(hidden, p_hh, p_hl, nh4);
    split_kernel<<<(unsigned)((nq4 + 255) / 256), 256>>>(w_qkv, p_wqh, p_wql, nq4);
    split_kernel<<<(unsigned)((no4 + 255) / 256), 256>>>(w_o, p_woh, p_wol, no4);

    // 1) qkv = hidden @ w_qkv^T   [4096, 6144] fp32
    tc_gemm128<<<dim3(QKVN / 128, (BB * SS) / 128, 1), 256, SM_TOTAL128>>>(
        p_hh, p_hl, p_wqh, p_wql, p_qkv,
        DD, DD, DD, QKVN, 0, 0, 0, 1.0f, 0);

    // 2) RoPE + RMSNorm + split (q/k/vt hi+lo)
    rope_norm_kernel<<<dim3(HKV * 6, SS, BB), 128>>>(cosp, sinp, qnw, knw);

    // 3) scores = scale * Q @ K^T (fp32), batched z = b*32+h, GQA K
    tc_gemm128<<<dim3(SS / 128, SS / 128, BB * NH), 256, SM_TOTAL128>>>(
        p_qhh, p_qll, p_kh, p_kl, p_sc,
        HD, HD, HD, SS,
        (long long)SS * HD, (long long)SS * HD, (long long)SS * SS,
        scale, 1);

    // 4) per-row softmax stats (max, 1/sumexp)
    stats_kernel<<<dim3(BB * NH * SS), 256>>>();

    // 5) attn = softmax(scores) @ Vt^T  (exp fused into A-staging) -> bf16 hi/lo
    tc_gemm_pv<<<dim3(1, SS / 128, BB * NH), 256, SM_TOTAL_PV>>>(
        p_sc, p_st, p_vth, p_vtl, p_ah, p_al);

    // 6) out = attn @ w_o^T (fp32)
    tc_gemm128<<<dim3(DD / 128, (BB * SS) / 128, 1), 256, SM_TOTAL128>>>(
        p_ah, p_al, p_woh, p_wol, out,
        DD, DD, DD, DD, 0, 0, 0, 1.0f, 0);
}